// round 5
// baseline (speedup 1.0000x reference)
#include <cuda_runtime.h>
#include <cstdint>

// ---------------------------------------------------------------------------
// Paged-attention prefill-extend, tf32 mma.sync flash-attention.
//
//   B=4, Q=512 new tokens per seq, P=2048 cached, L=2560, BS=16,
//   H=32 query heads, HK=8 kv heads (G=4), D=128, fp32 in/out.
//
// Key algebraic simplification: reference scatters fresh k/v into the caches
// at slots for positions P..L-1, then gathers all L positions. Since those
// slots are written with exactly the fresh rows, the gather for t >= P is
// identical to reading k/v directly. So we never modify the caches (which
// also keeps the kernel graph-replay-deterministic):
//     t <  P : row = k_cache[(bt[b][t/16]*16 + t%16)*HK + hk]
//     t >= P : row = k[(b*Q + t-P)*HK + hk]
//
// One CTA = (b, hk, 32-query-position tile) -> M=128 rows (32 pos x 4 g-heads
// sharing the same K/V), iterating N=64 keys at a time. 8 warps, each owning
// 16 M-rows. QK^T and PV both via mma.sync.m16n8k8 tf32 with fp32 accum.
// ---------------------------------------------------------------------------

#define DEVFN __device__ __forceinline__

namespace {

constexpr int B_  = 4;
constexpr int Q_  = 512;
constexpr int P_  = 2048;
constexpr int BS_ = 16;
constexpr int H_  = 32;
constexpr int HK_ = 8;
constexpr int D_  = 128;
constexpr int L_  = P_ + Q_;          // 2560
constexpr int G_  = H_ / HK_;         // 4
constexpr int NPAGES = L_ / BS_;      // 160

constexpr int TQ     = 32;            // query positions per block
constexpr int MTILE  = TQ * G_;       // 128 query rows per block
constexpr int NTILE  = 64;            // keys per mainloop iteration
constexpr int THREADS = 256;          // 8 warps, each owns 16 M-rows

// Shared-memory strides (floats), chosen mod 32 so every mma-fragment LDS
// pattern hits 32 distinct banks:
//   Q/K (row=lane/4 or lane>>2 groups, col=lane&3):  stride%32==4 -> conflict-free
//   V   (row=lane&3 groups, col=lane>>2):            stride%32==8 -> conflict-free
//   P   (A-fragment reads, row=lane>>2, col=lane&3): stride%32==4 -> conflict-free
constexpr int QS_STRIDE = 132;
constexpr int KS_STRIDE = 132;
constexpr int VS_STRIDE = 136;
constexpr int PS_STRIDE = 68;

constexpr int QS_OFF = 0;
constexpr int KS_OFF = QS_OFF + MTILE * QS_STRIDE;   // 16896
constexpr int VS_OFF = KS_OFF + NTILE * KS_STRIDE;   // 25344
constexpr int PS_OFF = VS_OFF + NTILE * VS_STRIDE;   // 34048
constexpr int SMEM_FLOATS = PS_OFF + MTILE * PS_STRIDE;  // 42752
constexpr int SMEM_BYTES  = SMEM_FLOATS * 4;             // 171008 B

DEVFN uint32_t f2tf32(float x) {
    uint32_t r;
    asm("cvt.rna.tf32.f32 %0, %1;" : "=r"(r) : "f"(x));
    return r;
}

DEVFN void mma_tf32(float& c0, float& c1, float& c2, float& c3,
                    uint32_t a0, uint32_t a1, uint32_t a2, uint32_t a3,
                    uint32_t b0, uint32_t b1) {
    asm volatile(
        "mma.sync.aligned.m16n8k8.row.col.f32.tf32.tf32.f32 "
        "{%0,%1,%2,%3}, {%4,%5,%6,%7}, {%8,%9}, {%0,%1,%2,%3};"
        : "+f"(c0), "+f"(c1), "+f"(c2), "+f"(c3)
        : "r"(a0), "r"(a1), "r"(a2), "r"(a3), "r"(b0), "r"(b1));
}

// Pointer to the D=128 fp32 row for key/value position t of (b, hk).
DEVFN const float4* kv_row(const float* __restrict__ cache,
                           const float* __restrict__ fresh,
                           const int* __restrict__ bt,
                           int b, int hk, int t) {
    if (t < P_) {
        int page = bt[b * NPAGES + (t >> 4)];
        long slot = (long)page * BS_ + (t & 15);
        return reinterpret_cast<const float4*>(cache + (slot * HK_ + hk) * D_);
    }
    long row = (long)(b * Q_ + (t - P_)) * HK_ + hk;
    return reinterpret_cast<const float4*>(fresh + row * D_);
}

__global__ __launch_bounds__(THREADS, 1)
void attn_kernel(const float* __restrict__ q,  const float* __restrict__ k,
                 const float* __restrict__ v,  const float* __restrict__ kc,
                 const float* __restrict__ vc, const int*   __restrict__ bt,
                 float* __restrict__ out) {
    extern __shared__ float sm[];
    float* QS = sm + QS_OFF;
    float* KS = sm + KS_OFF;
    float* VS = sm + VS_OFF;
    float* PS = sm + PS_OFF;

    const int tid  = threadIdx.x;
    const int warp = tid >> 5;
    const int lane = tid & 31;
    const int gp   = lane >> 2;   // groupID
    const int tig  = lane & 3;    // threadID_in_group

    const int qt = blockIdx.x;    // query-position tile (0..15)
    const int hk = blockIdx.y;    // kv head (0..7)
    const int b  = blockIdx.z;    // batch (0..3)

    const int qpos0 = P_ + qt * TQ;  // smallest query position in this block

    // Fold softmax scale AND log2(e) into Q, so scores live in the exp2 domain.
    const float qscale = 0.088388347648318447f /* D^-1/2 */ *
                         1.4426950408889634f   /* log2(e) */;

    // ---- Load + scale + tf32-round the Q tile (rows m = qi_local*4 + g) ----
    for (int i = tid; i < MTILE * 32; i += THREADS) {
        int m = i >> 5, c = i & 31;
        int qi = qt * TQ + (m >> 2);
        int g  = m & 3;
        const float4* qp = reinterpret_cast<const float4*>(
            q + ((long)(b * Q_ + qi) * H_ + hk * G_ + g) * D_);
        float4 x = qp[c];
        float* dst = QS + m * QS_STRIDE + c * 4;
        dst[0] = __uint_as_float(f2tf32(x.x * qscale));
        dst[1] = __uint_as_float(f2tf32(x.y * qscale));
        dst[2] = __uint_as_float(f2tf32(x.z * qscale));
        dst[3] = __uint_as_float(f2tf32(x.w * qscale));
    }

    // Per-thread fragment rows (mma m16n8: rows gp and gp+8 within warp tile).
    const int r0 = warp * 16 + gp;
    const int r1 = r0 + 8;
    const int qpos_r0 = qpos0 + (r0 >> 2);
    const int qpos_r1 = qpos0 + (r1 >> 2);

    float m0 = -1e30f, m1 = -1e30f;   // running row maxima (log2 domain)
    float l0 = 0.f,    l1 = 0.f;      // running row sums
    float o[16][4];                   // O accumulator: 16 n-tiles of 8 cols
    #pragma unroll
    for (int i = 0; i < 16; i++) { o[i][0] = o[i][1] = o[i][2] = o[i][3] = 0.f; }

    const int nkt = (qpos0 + TQ + NTILE - 1) / NTILE;   // key tiles needed

    for (int kt = 0; kt < nkt; kt++) {
        __syncthreads();   // previous tile's K/V smem reads complete
        // ---- Load K/V tile (64 keys x 128) with tf32 rounding ----
        for (int i = tid; i < NTILE * 32; i += THREADS) {
            int j = i >> 5, c = i & 31;
            int t = kt * NTILE + j;
            float4 kx = kv_row(kc, k, bt, b, hk, t)[c];
            float* kd = KS + j * KS_STRIDE + c * 4;
            kd[0] = __uint_as_float(f2tf32(kx.x));
            kd[1] = __uint_as_float(f2tf32(kx.y));
            kd[2] = __uint_as_float(f2tf32(kx.z));
            kd[3] = __uint_as_float(f2tf32(kx.w));
            float4 vx = kv_row(vc, v, bt, b, hk, t)[c];
            float* vd = VS + j * VS_STRIDE + c * 4;
            vd[0] = __uint_as_float(f2tf32(vx.x));
            vd[1] = __uint_as_float(f2tf32(vx.y));
            vd[2] = __uint_as_float(f2tf32(vx.z));
            vd[3] = __uint_as_float(f2tf32(vx.w));
        }
        __syncthreads();

        // ---- S = (Q*scale) K^T : warp computes its 16 rows x 64 keys ----
        float s[8][4];
        #pragma unroll
        for (int nt = 0; nt < 8; nt++) { s[nt][0]=s[nt][1]=s[nt][2]=s[nt][3]=0.f; }
        #pragma unroll
        for (int kk = 0; kk < 16; kk++) {            // D/8 k-steps
            uint32_t a0 = __float_as_uint(QS[r0 * QS_STRIDE + kk * 8 + tig]);
            uint32_t a1 = __float_as_uint(QS[r1 * QS_STRIDE + kk * 8 + tig]);
            uint32_t a2 = __float_as_uint(QS[r0 * QS_STRIDE + kk * 8 + tig + 4]);
            uint32_t a3 = __float_as_uint(QS[r1 * QS_STRIDE + kk * 8 + tig + 4]);
            #pragma unroll
            for (int nt = 0; nt < 8; nt++) {         // 64 keys / 8
                uint32_t b0 = __float_as_uint(KS[(nt*8 + gp) * KS_STRIDE + kk*8 + tig]);
                uint32_t b1 = __float_as_uint(KS[(nt*8 + gp) * KS_STRIDE + kk*8 + tig + 4]);
                mma_tf32(s[nt][0], s[nt][1], s[nt][2], s[nt][3],
                         a0, a1, a2, a3, b0, b1);
            }
        }

        // ---- Causal mask (only tiles overlapping the query region) ----
        if (kt * NTILE + NTILE - 1 > qpos0) {
            #pragma unroll
            for (int nt = 0; nt < 8; nt++) {
                int t0 = kt * NTILE + nt * 8 + 2 * tig;
                if (t0     > qpos_r0) s[nt][0] = -1e30f;
                if (t0 + 1 > qpos_r0) s[nt][1] = -1e30f;
                if (t0     > qpos_r1) s[nt][2] = -1e30f;
                if (t0 + 1 > qpos_r1) s[nt][3] = -1e30f;
            }
        }

        // ---- Online softmax (exp2 domain) ----
        float mx0 = -1e30f, mx1 = -1e30f;
        #pragma unroll
        for (int nt = 0; nt < 8; nt++) {
            mx0 = fmaxf(mx0, fmaxf(s[nt][0], s[nt][1]));
            mx1 = fmaxf(mx1, fmaxf(s[nt][2], s[nt][3]));
        }
        mx0 = fmaxf(mx0, __shfl_xor_sync(0xffffffffu, mx0, 1));
        mx0 = fmaxf(mx0, __shfl_xor_sync(0xffffffffu, mx0, 2));
        mx1 = fmaxf(mx1, __shfl_xor_sync(0xffffffffu, mx1, 1));
        mx1 = fmaxf(mx1, __shfl_xor_sync(0xffffffffu, mx1, 2));

        float nm0 = fmaxf(m0, mx0), nm1 = fmaxf(m1, mx1);
        float al0 = exp2f(m0 - nm0), al1 = exp2f(m1 - nm1);
        m0 = nm0; m1 = nm1;

        float ts0 = 0.f, ts1 = 0.f;
        #pragma unroll
        for (int nt = 0; nt < 8; nt++) {
            float p0 = exp2f(s[nt][0] - m0), p1 = exp2f(s[nt][1] - m0);
            float p2 = exp2f(s[nt][2] - m1), p3 = exp2f(s[nt][3] - m1);
            ts0 += p0 + p1;
            ts1 += p2 + p3;
            float* d0 = PS + r0 * PS_STRIDE + nt * 8 + 2 * tig;
            d0[0] = __uint_as_float(f2tf32(p0));
            d0[1] = __uint_as_float(f2tf32(p1));
            float* d1 = PS + r1 * PS_STRIDE + nt * 8 + 2 * tig;
            d1[0] = __uint_as_float(f2tf32(p2));
            d1[1] = __uint_as_float(f2tf32(p3));
        }
        ts0 += __shfl_xor_sync(0xffffffffu, ts0, 1);
        ts0 += __shfl_xor_sync(0xffffffffu, ts0, 2);
        ts1 += __shfl_xor_sync(0xffffffffu, ts1, 1);
        ts1 += __shfl_xor_sync(0xffffffffu, ts1, 2);
        l0 = l0 * al0 + ts0;
        l1 = l1 * al1 + ts1;

        #pragma unroll
        for (int nt = 0; nt < 16; nt++) {
            o[nt][0] *= al0; o[nt][1] *= al0;
            o[nt][2] *= al1; o[nt][3] *= al1;
        }
        __syncwarp();   // PS writes (C-layout) visible to PV A-fragment reads

        // ---- O += P V : 64-key contraction, 128 output cols ----
        #pragma unroll
        for (int kk = 0; kk < 8; kk++) {             // 64 keys / 8
            uint32_t a0 = __float_as_uint(PS[r0 * PS_STRIDE + kk * 8 + tig]);
            uint32_t a1 = __float_as_uint(PS[r1 * PS_STRIDE + kk * 8 + tig]);
            uint32_t a2 = __float_as_uint(PS[r0 * PS_STRIDE + kk * 8 + tig + 4]);
            uint32_t a3 = __float_as_uint(PS[r1 * PS_STRIDE + kk * 8 + tig + 4]);
            #pragma unroll
            for (int nt = 0; nt < 16; nt++) {        // D/8 output n-tiles
                uint32_t b0 = __float_as_uint(VS[(kk*8 + tig)     * VS_STRIDE + nt*8 + gp]);
                uint32_t b1 = __float_as_uint(VS[(kk*8 + tig + 4) * VS_STRIDE + nt*8 + gp]);
                mma_tf32(o[nt][0], o[nt][1], o[nt][2], o[nt][3],
                         a0, a1, a2, a3, b0, b1);
            }
        }
    }

    // ---- Epilogue: normalize and store (fp32 output) ----
    const float inv0 = 1.f / l0;
    const float inv1 = 1.f / l1;
    const long orow0 = ((long)(b * Q_ + qt * TQ + (r0 >> 2)) * H_ + hk * G_ + (r0 & 3)) * D_;
    const long orow1 = ((long)(b * Q_ + qt * TQ + (r1 >> 2)) * H_ + hk * G_ + (r1 & 3)) * D_;
    #pragma unroll
    for (int nt = 0; nt < 16; nt++) {
        int cc = nt * 8 + 2 * tig;
        float2 w0 = make_float2(o[nt][0] * inv0, o[nt][1] * inv0);
        float2 w1 = make_float2(o[nt][2] * inv1, o[nt][3] * inv1);
        *reinterpret_cast<float2*>(out + orow0 + cc) = w0;
        *reinterpret_cast<float2*>(out + orow1 + cc) = w1;
    }
}

}  // namespace

extern "C" void kernel_launch(void* const* d_in, const int* in_sizes, int n_in,
                              void* d_out, int out_size) {
    const float* q  = (const float*)d_in[0];
    const float* k  = (const float*)d_in[1];
    const float* v  = (const float*)d_in[2];
    const float* kc = (const float*)d_in[3];
    const float* vc = (const float*)d_in[4];
    const int*   bt = (const int*)d_in[5];
    float* out = (float*)d_out;

    // Idempotent, capture-safe (not a stream op, not an allocation).
    cudaFuncSetAttribute(attn_kernel,
                         cudaFuncAttributeMaxDynamicSharedMemorySize, SMEM_BYTES);

    dim3 grid(Q_ / TQ, HK_, B_);   // qt fastest -> same-(b,hk) blocks share L2
    attn_kernel<<<grid, THREADS, SMEM_BYTES>>>(q, k, v, kc, vc, bt, out);
}

// round 6
// speedup vs baseline: 1.4321x; 1.4321x over previous
#include <cuda_runtime.h>
#include <cstdint>

// ---------------------------------------------------------------------------
// Paged-attention prefill-extend, tf32 mma.sync flash-attention, v2:
// warp-specialized producer/consumer pipeline with double-buffered K/V
// and shuffle-based P transpose (no PS smem round-trip).
//
//   B=4, Q=512 new tokens per seq, P=2048 cached, L=2560, BS=16,
//   H=32 query heads, HK=8 kv heads (G=4), D=128, fp32 in/out.
//
// Cache-scatter elimination: reference writes fresh k/v into the caches at
// slots for positions P..L-1, then gathers; the gather for t >= P returns
// exactly the fresh rows, so we read them directly and never mutate inputs.
//
// One CTA = (b, hk, 32-query tile) -> M=128 rows (32 pos x G=4 heads sharing
// K/V), N=64 keys per mainloop iteration.
//   warps 0..7  : compute (16 M-rows each), QK^T + online softmax + PV via
//                 mma.sync.m16n8k8 tf32/f32.
//   warps 8..11 : producers — LDG + tf32-round + STS of tile kt+1 into the
//                 other half of a double buffer while consumers work on kt.
// ---------------------------------------------------------------------------

#define DEVFN __device__ __forceinline__

namespace {

constexpr int B_  = 4;
constexpr int Q_  = 512;
constexpr int P_  = 2048;
constexpr int BS_ = 16;
constexpr int H_  = 32;
constexpr int HK_ = 8;
constexpr int D_  = 128;
constexpr int L_  = P_ + Q_;          // 2560
constexpr int G_  = H_ / HK_;         // 4
constexpr int NPAGES = L_ / BS_;      // 160

constexpr int TQ      = 32;           // query positions per block
constexpr int MTILE   = TQ * G_;      // 128 query rows per block
constexpr int NTILE   = 64;           // keys per mainloop iteration
constexpr int NCWARP  = 8;            // compute warps
constexpr int NPWARP  = 4;            // producer warps
constexpr int THREADS = (NCWARP + NPWARP) * 32;   // 384

// Smem strides (floats), mod-32 residues keep all fragment LDS conflict-free:
//   Q/K (A/B frags, col=tig, tig+4): stride%32==4
//   V   (B frags, row=8kk+tig, col=8nt+gp): stride%32==8
constexpr int QS_STRIDE = 132;
constexpr int KS_STRIDE = 132;
constexpr int VS_STRIDE = 136;

constexpr int QS_OFF = 0;
constexpr int KS_OFF = QS_OFF + MTILE * QS_STRIDE;        // 16896
constexpr int KS_BUF = NTILE * KS_STRIDE;                 // 8448
constexpr int VS_OFF = KS_OFF + 2 * KS_BUF;               // 33792
constexpr int VS_BUF = NTILE * VS_STRIDE;                 // 8704
constexpr int SMEM_FLOATS = VS_OFF + 2 * VS_BUF;          // 51200
constexpr int SMEM_BYTES  = SMEM_FLOATS * 4;              // 204800 B

DEVFN uint32_t f2tf32(float x) {
    uint32_t r;
    asm("cvt.rna.tf32.f32 %0, %1;" : "=r"(r) : "f"(x));
    return r;
}

DEVFN void mma_tf32(float& c0, float& c1, float& c2, float& c3,
                    uint32_t a0, uint32_t a1, uint32_t a2, uint32_t a3,
                    uint32_t b0, uint32_t b1) {
    asm volatile(
        "mma.sync.aligned.m16n8k8.row.col.f32.tf32.tf32.f32 "
        "{%0,%1,%2,%3}, {%4,%5,%6,%7}, {%8,%9}, {%0,%1,%2,%3};"
        : "+f"(c0), "+f"(c1), "+f"(c2), "+f"(c3)
        : "r"(a0), "r"(a1), "r"(a2), "r"(a3), "r"(b0), "r"(b1));
}

// Pointer to the D=128 fp32 row for key/value position t of (b, hk).
DEVFN const float4* kv_row(const float* __restrict__ cache,
                           const float* __restrict__ fresh,
                           const int* __restrict__ bt,
                           int b, int hk, int t) {
    if (t < P_) {
        int page = bt[b * NPAGES + (t >> 4)];
        long slot = (long)page * BS_ + (t & 15);
        return reinterpret_cast<const float4*>(cache + (slot * HK_ + hk) * D_);
    }
    long row = (long)(b * Q_ + (t - P_)) * HK_ + hk;
    return reinterpret_cast<const float4*>(fresh + row * D_);
}

// Producer: load K/V tile kt (64 keys x 128), tf32-round, store to buffer.
DEVFN void fill_tile(float* __restrict__ KSb, float* __restrict__ VSb,
                     const float* __restrict__ k, const float* __restrict__ v,
                     const float* __restrict__ kc, const float* __restrict__ vc,
                     const int* __restrict__ bt,
                     int b, int hk, int kt, int pt) {
    #pragma unroll
    for (int i = pt; i < NTILE * 32; i += NPWARP * 32) {
        int j = i >> 5, c = i & 31;
        int t = kt * NTILE + j;
        float4 kx = kv_row(kc, k, bt, b, hk, t)[c];
        float4 vx = kv_row(vc, v, bt, b, hk, t)[c];
        float4 kw, vw;
        kw.x = __uint_as_float(f2tf32(kx.x)); kw.y = __uint_as_float(f2tf32(kx.y));
        kw.z = __uint_as_float(f2tf32(kx.z)); kw.w = __uint_as_float(f2tf32(kx.w));
        vw.x = __uint_as_float(f2tf32(vx.x)); vw.y = __uint_as_float(f2tf32(vx.y));
        vw.z = __uint_as_float(f2tf32(vx.z)); vw.w = __uint_as_float(f2tf32(vx.w));
        *reinterpret_cast<float4*>(KSb + j * KS_STRIDE + c * 4) = kw;
        *reinterpret_cast<float4*>(VSb + j * VS_STRIDE + c * 4) = vw;
    }
}

__global__ __launch_bounds__(THREADS, 1)
void attn_kernel(const float* __restrict__ q,  const float* __restrict__ k,
                 const float* __restrict__ v,  const float* __restrict__ kc,
                 const float* __restrict__ vc, const int*   __restrict__ bt,
                 float* __restrict__ out) {
    extern __shared__ float sm[];
    float* QS = sm + QS_OFF;

    const int tid  = threadIdx.x;
    const int warp = tid >> 5;
    const int lane = tid & 31;
    const int gp   = lane >> 2;   // groupID
    const int tig  = lane & 3;    // threadID_in_group

    const int qt = blockIdx.x;    // query-position tile (0..15)
    const int hk = blockIdx.y;    // kv head (0..7)
    const int b  = blockIdx.z;    // batch (0..3)

    const int qpos0 = P_ + qt * TQ;
    const int nkt   = (qpos0 + TQ + NTILE - 1) / NTILE;   // key tiles needed

    const bool is_producer = (warp >= NCWARP);
    const int  pt = tid - NCWARP * 32;   // producer-thread index (0..127)

    // Fold softmax scale AND log2(e) into Q, so scores are in the exp2 domain.
    const float qscale = 0.088388347648318447f * 1.4426950408889634f;

    // ---- Cooperative Q load + scale + tf32 rounding (all 384 threads) ----
    for (int i = tid; i < MTILE * 32; i += THREADS) {
        int m = i >> 5, c = i & 31;
        int qi = qt * TQ + (m >> 2);
        int g  = m & 3;
        const float4* qp = reinterpret_cast<const float4*>(
            q + ((long)(b * Q_ + qi) * H_ + hk * G_ + g) * D_);
        float4 x = qp[c];
        float4 w;
        w.x = __uint_as_float(f2tf32(x.x * qscale));
        w.y = __uint_as_float(f2tf32(x.y * qscale));
        w.z = __uint_as_float(f2tf32(x.z * qscale));
        w.w = __uint_as_float(f2tf32(x.w * qscale));
        *reinterpret_cast<float4*>(QS + m * QS_STRIDE + c * 4) = w;
    }

    // Producers prefill buffer 0 with tile 0 (overlaps consumers' Q load).
    if (is_producer) {
        fill_tile(sm + KS_OFF, sm + VS_OFF, k, v, kc, vc, bt, b, hk, 0, pt);
    }
    __syncthreads();   // Q tile + K/V tile 0 ready

    // Per-thread fragment rows (mma m16n8: rows gp and gp+8 in warp tile).
    const int r0 = warp * 16 + gp;          // (only meaningful for consumers)
    const int r1 = r0 + 8;
    const int qpos_r0 = qpos0 + (r0 >> 2);
    const int qpos_r1 = qpos0 + (r1 >> 2);

    float m0 = -1e30f, m1 = -1e30f;   // running row maxima (log2 domain)
    float l0 = 0.f,    l1 = 0.f;      // running row sums
    float o[16][4];                   // O accumulator: 16 n-tiles of 8 cols
    #pragma unroll
    for (int i = 0; i < 16; i++) { o[i][0] = o[i][1] = o[i][2] = o[i][3] = 0.f; }

    const int src0 = (lane & 28) | (tig >> 1);   // P-transpose shuffle sources
    const int src2 = src0 + 2;
    const bool oddc = (tig & 1);

    for (int kt = 0; kt < nkt; kt++) {
        const int buf = kt & 1;
        float* KS = sm + KS_OFF + buf * KS_BUF;
        float* VS = sm + VS_OFF + buf * VS_BUF;

        if (is_producer) {
            // Fill the other buffer with the next tile while consumers work.
            if (kt + 1 < nkt) {
                fill_tile(sm + KS_OFF + (buf ^ 1) * KS_BUF,
                          sm + VS_OFF + (buf ^ 1) * VS_BUF,
                          k, v, kc, vc, bt, b, hk, kt + 1, pt);
            }
        } else {
            // ---- S = (Q*scale) K^T : 16 rows x 64 keys per warp ----
            float s[8][4];
            #pragma unroll
            for (int nt = 0; nt < 8; nt++) { s[nt][0]=s[nt][1]=s[nt][2]=s[nt][3]=0.f; }
            #pragma unroll
            for (int kk = 0; kk < 16; kk++) {            // D/8 k-steps
                uint32_t a0 = __float_as_uint(QS[r0 * QS_STRIDE + kk * 8 + tig]);
                uint32_t a1 = __float_as_uint(QS[r1 * QS_STRIDE + kk * 8 + tig]);
                uint32_t a2 = __float_as_uint(QS[r0 * QS_STRIDE + kk * 8 + tig + 4]);
                uint32_t a3 = __float_as_uint(QS[r1 * QS_STRIDE + kk * 8 + tig + 4]);
                #pragma unroll
                for (int nt = 0; nt < 8; nt++) {         // 64 keys / 8
                    uint32_t b0 = __float_as_uint(KS[(nt*8 + gp) * KS_STRIDE + kk*8 + tig]);
                    uint32_t b1 = __float_as_uint(KS[(nt*8 + gp) * KS_STRIDE + kk*8 + tig + 4]);
                    mma_tf32(s[nt][0], s[nt][1], s[nt][2], s[nt][3],
                             a0, a1, a2, a3, b0, b1);
                }
            }

            // ---- Causal mask (only tiles overlapping the query region) ----
            if (kt * NTILE + NTILE - 1 > qpos0) {
                #pragma unroll
                for (int nt = 0; nt < 8; nt++) {
                    int t0 = kt * NTILE + nt * 8 + 2 * tig;
                    if (t0     > qpos_r0) s[nt][0] = -1e30f;
                    if (t0 + 1 > qpos_r0) s[nt][1] = -1e30f;
                    if (t0     > qpos_r1) s[nt][2] = -1e30f;
                    if (t0 + 1 > qpos_r1) s[nt][3] = -1e30f;
                }
            }

            // ---- Online softmax (exp2 domain); exp'd P overwrites s ----
            float mx0 = -1e30f, mx1 = -1e30f;
            #pragma unroll
            for (int nt = 0; nt < 8; nt++) {
                mx0 = fmaxf(mx0, fmaxf(s[nt][0], s[nt][1]));
                mx1 = fmaxf(mx1, fmaxf(s[nt][2], s[nt][3]));
            }
            mx0 = fmaxf(mx0, __shfl_xor_sync(0xffffffffu, mx0, 1));
            mx0 = fmaxf(mx0, __shfl_xor_sync(0xffffffffu, mx0, 2));
            mx1 = fmaxf(mx1, __shfl_xor_sync(0xffffffffu, mx1, 1));
            mx1 = fmaxf(mx1, __shfl_xor_sync(0xffffffffu, mx1, 2));

            float nm0 = fmaxf(m0, mx0), nm1 = fmaxf(m1, mx1);
            float al0 = exp2f(m0 - nm0), al1 = exp2f(m1 - nm1);
            m0 = nm0; m1 = nm1;

            float ts0 = 0.f, ts1 = 0.f;
            #pragma unroll
            for (int nt = 0; nt < 8; nt++) {
                s[nt][0] = exp2f(s[nt][0] - m0);
                s[nt][1] = exp2f(s[nt][1] - m0);
                s[nt][2] = exp2f(s[nt][2] - m1);
                s[nt][3] = exp2f(s[nt][3] - m1);
                ts0 += s[nt][0] + s[nt][1];
                ts1 += s[nt][2] + s[nt][3];
            }
            ts0 += __shfl_xor_sync(0xffffffffu, ts0, 1);
            ts0 += __shfl_xor_sync(0xffffffffu, ts0, 2);
            ts1 += __shfl_xor_sync(0xffffffffu, ts1, 1);
            ts1 += __shfl_xor_sync(0xffffffffu, ts1, 2);
            l0 = l0 * al0 + ts0;
            l1 = l1 * al1 + ts1;

            #pragma unroll
            for (int nt = 0; nt < 16; nt++) {
                o[nt][0] *= al0; o[nt][1] *= al0;
                o[nt][2] *= al1; o[nt][3] *= al1;
            }

            // ---- O += P V, with P transposed C->A layout via shuffles ----
            #pragma unroll
            for (int kk = 0; kk < 8; kk++) {             // 64 keys / 8
                // A-frag element (r, 8kk+c): owner lane (gp, c>>1), comp c&1.
                float x00 = __shfl_sync(0xffffffffu, s[kk][0], src0);
                float x01 = __shfl_sync(0xffffffffu, s[kk][1], src0);
                float x10 = __shfl_sync(0xffffffffu, s[kk][2], src0);
                float x11 = __shfl_sync(0xffffffffu, s[kk][3], src0);
                float y00 = __shfl_sync(0xffffffffu, s[kk][0], src2);
                float y01 = __shfl_sync(0xffffffffu, s[kk][1], src2);
                float y10 = __shfl_sync(0xffffffffu, s[kk][2], src2);
                float y11 = __shfl_sync(0xffffffffu, s[kk][3], src2);
                uint32_t a0 = f2tf32(oddc ? x01 : x00);
                uint32_t a1 = f2tf32(oddc ? x11 : x10);
                uint32_t a2 = f2tf32(oddc ? y01 : y00);
                uint32_t a3 = f2tf32(oddc ? y11 : y10);
                #pragma unroll
                for (int nt = 0; nt < 16; nt++) {        // D/8 output n-tiles
                    uint32_t b0 = __float_as_uint(VS[(kk*8 + tig)     * VS_STRIDE + nt*8 + gp]);
                    uint32_t b1 = __float_as_uint(VS[(kk*8 + tig + 4) * VS_STRIDE + nt*8 + gp]);
                    mma_tf32(o[nt][0], o[nt][1], o[nt][2], o[nt][3],
                             a0, a1, a2, a3, b0, b1);
                }
            }
        }

        __syncthreads();   // next buffer filled; current buffer consumed
    }

    // ---- Epilogue: normalize and store (compute warps only) ----
    if (!is_producer) {
        const float inv0 = 1.f / l0;
        const float inv1 = 1.f / l1;
        const long orow0 = ((long)(b * Q_ + qt * TQ + (r0 >> 2)) * H_ + hk * G_ + (r0 & 3)) * D_;
        const long orow1 = ((long)(b * Q_ + qt * TQ + (r1 >> 2)) * H_ + hk * G_ + (r1 & 3)) * D_;
        #pragma unroll
        for (int nt = 0; nt < 16; nt++) {
            int cc = nt * 8 + 2 * tig;
            float2 w0 = make_float2(o[nt][0] * inv0, o[nt][1] * inv0);
            float2 w1 = make_float2(o[nt][2] * inv1, o[nt][3] * inv1);
            *reinterpret_cast<float2*>(out + orow0 + cc) = w0;
            *reinterpret_cast<float2*>(out + orow1 + cc) = w1;
        }
    }
}

}  // namespace

extern "C" void kernel_launch(void* const* d_in, const int* in_sizes, int n_in,
                              void* d_out, int out_size) {
    const float* q  = (const float*)d_in[0];
    const float* k  = (const float*)d_in[1];
    const float* v  = (const float*)d_in[2];
    const float* kc = (const float*)d_in[3];
    const float* vc = (const float*)d_in[4];
    const int*   bt = (const int*)d_in[5];
    float* out = (float*)d_out;

    cudaFuncSetAttribute(attn_kernel,
                         cudaFuncAttributeMaxDynamicSharedMemorySize, SMEM_BYTES);

    dim3 grid(Q_ / TQ, HK_, B_);   // qt fastest -> same-(b,hk) blocks share L2
    attn_kernel<<<grid, THREADS, SMEM_BYTES>>>(q, k, v, kc, vc, bt, out);
}

// round 7
// speedup vs baseline: 1.4327x; 1.0004x over previous
#include <cuda_runtime.h>
#include <cstdint>

// ---------------------------------------------------------------------------
// Paged-attention prefill-extend, tf32 mma.sync flash-attention, v2:
// warp-specialized producer/consumer pipeline with double-buffered K/V
// and shuffle-based P transpose (no PS smem round-trip).
//
//   B=4, Q=512 new tokens per seq, P=2048 cached, L=2560, BS=16,
//   H=32 query heads, HK=8 kv heads (G=4), D=128, fp32 in/out.
//
// Cache-scatter elimination: reference writes fresh k/v into the caches at
// slots for positions P..L-1, then gathers; the gather for t >= P returns
// exactly the fresh rows, so we read them directly and never mutate inputs.
//
// One CTA = (b, hk, 32-query tile) -> M=128 rows (32 pos x G=4 heads sharing
// K/V), N=64 keys per mainloop iteration.
//   warps 0..7  : compute (16 M-rows each), QK^T + online softmax + PV via
//                 mma.sync.m16n8k8 tf32/f32.
//   warps 8..11 : producers — LDG + tf32-round + STS of tile kt+1 into the
//                 other half of a double buffer while consumers work on kt.
// ---------------------------------------------------------------------------

#define DEVFN __device__ __forceinline__

namespace {

constexpr int B_  = 4;
constexpr int Q_  = 512;
constexpr int P_  = 2048;
constexpr int BS_ = 16;
constexpr int H_  = 32;
constexpr int HK_ = 8;
constexpr int D_  = 128;
constexpr int L_  = P_ + Q_;          // 2560
constexpr int G_  = H_ / HK_;         // 4
constexpr int NPAGES = L_ / BS_;      // 160

constexpr int TQ      = 32;           // query positions per block
constexpr int MTILE   = TQ * G_;      // 128 query rows per block
constexpr int NTILE   = 64;           // keys per mainloop iteration
constexpr int NCWARP  = 8;            // compute warps
constexpr int NPWARP  = 4;            // producer warps
constexpr int THREADS = (NCWARP + NPWARP) * 32;   // 384

// Smem strides (floats), mod-32 residues keep all fragment LDS conflict-free:
//   Q/K (A/B frags, col=tig, tig+4): stride%32==4
//   V   (B frags, row=8kk+tig, col=8nt+gp): stride%32==8
constexpr int QS_STRIDE = 132;
constexpr int KS_STRIDE = 132;
constexpr int VS_STRIDE = 136;

constexpr int QS_OFF = 0;
constexpr int KS_OFF = QS_OFF + MTILE * QS_STRIDE;        // 16896
constexpr int KS_BUF = NTILE * KS_STRIDE;                 // 8448
constexpr int VS_OFF = KS_OFF + 2 * KS_BUF;               // 33792
constexpr int VS_BUF = NTILE * VS_STRIDE;                 // 8704
constexpr int SMEM_FLOATS = VS_OFF + 2 * VS_BUF;          // 51200
constexpr int SMEM_BYTES  = SMEM_FLOATS * 4;              // 204800 B

DEVFN uint32_t f2tf32(float x) {
    uint32_t r;
    asm("cvt.rna.tf32.f32 %0, %1;" : "=r"(r) : "f"(x));
    return r;
}

DEVFN void mma_tf32(float& c0, float& c1, float& c2, float& c3,
                    uint32_t a0, uint32_t a1, uint32_t a2, uint32_t a3,
                    uint32_t b0, uint32_t b1) {
    asm volatile(
        "mma.sync.aligned.m16n8k8.row.col.f32.tf32.tf32.f32 "
        "{%0,%1,%2,%3}, {%4,%5,%6,%7}, {%8,%9}, {%0,%1,%2,%3};"
        : "+f"(c0), "+f"(c1), "+f"(c2), "+f"(c3)
        : "r"(a0), "r"(a1), "r"(a2), "r"(a3), "r"(b0), "r"(b1));
}

// Pointer to the D=128 fp32 row for key/value position t of (b, hk).
DEVFN const float4* kv_row(const float* __restrict__ cache,
                           const float* __restrict__ fresh,
                           const int* __restrict__ bt,
                           int b, int hk, int t) {
    if (t < P_) {
        int page = bt[b * NPAGES + (t >> 4)];
        long slot = (long)page * BS_ + (t & 15);
        return reinterpret_cast<const float4*>(cache + (slot * HK_ + hk) * D_);
    }
    long row = (long)(b * Q_ + (t - P_)) * HK_ + hk;
    return reinterpret_cast<const float4*>(fresh + row * D_);
}

// Producer: load K/V tile kt (64 keys x 128), tf32-round, store to buffer.
DEVFN void fill_tile(float* __restrict__ KSb, float* __restrict__ VSb,
                     const float* __restrict__ k, const float* __restrict__ v,
                     const float* __restrict__ kc, const float* __restrict__ vc,
                     const int* __restrict__ bt,
                     int b, int hk, int kt, int pt) {
    #pragma unroll
    for (int i = pt; i < NTILE * 32; i += NPWARP * 32) {
        int j = i >> 5, c = i & 31;
        int t = kt * NTILE + j;
        float4 kx = kv_row(kc, k, bt, b, hk, t)[c];
        float4 vx = kv_row(vc, v, bt, b, hk, t)[c];
        float4 kw, vw;
        kw.x = __uint_as_float(f2tf32(kx.x)); kw.y = __uint_as_float(f2tf32(kx.y));
        kw.z = __uint_as_float(f2tf32(kx.z)); kw.w = __uint_as_float(f2tf32(kx.w));
        vw.x = __uint_as_float(f2tf32(vx.x)); vw.y = __uint_as_float(f2tf32(vx.y));
        vw.z = __uint_as_float(f2tf32(vx.z)); vw.w = __uint_as_float(f2tf32(vx.w));
        *reinterpret_cast<float4*>(KSb + j * KS_STRIDE + c * 4) = kw;
        *reinterpret_cast<float4*>(VSb + j * VS_STRIDE + c * 4) = vw;
    }
}

__global__ __launch_bounds__(THREADS, 1)
void attn_kernel(const float* __restrict__ q,  const float* __restrict__ k,
                 const float* __restrict__ v,  const float* __restrict__ kc,
                 const float* __restrict__ vc, const int*   __restrict__ bt,
                 float* __restrict__ out) {
    extern __shared__ float sm[];
    float* QS = sm + QS_OFF;

    const int tid  = threadIdx.x;
    const int warp = tid >> 5;
    const int lane = tid & 31;
    const int gp   = lane >> 2;   // groupID
    const int tig  = lane & 3;    // threadID_in_group

    const int qt = blockIdx.x;    // query-position tile (0..15)
    const int hk = blockIdx.y;    // kv head (0..7)
    const int b  = blockIdx.z;    // batch (0..3)

    const int qpos0 = P_ + qt * TQ;
    const int nkt   = (qpos0 + TQ + NTILE - 1) / NTILE;   // key tiles needed

    const bool is_producer = (warp >= NCWARP);
    const int  pt = tid - NCWARP * 32;   // producer-thread index (0..127)

    // Fold softmax scale AND log2(e) into Q, so scores are in the exp2 domain.
    const float qscale = 0.088388347648318447f * 1.4426950408889634f;

    // ---- Cooperative Q load + scale + tf32 rounding (all 384 threads) ----
    for (int i = tid; i < MTILE * 32; i += THREADS) {
        int m = i >> 5, c = i & 31;
        int qi = qt * TQ + (m >> 2);
        int g  = m & 3;
        const float4* qp = reinterpret_cast<const float4*>(
            q + ((long)(b * Q_ + qi) * H_ + hk * G_ + g) * D_);
        float4 x = qp[c];
        float4 w;
        w.x = __uint_as_float(f2tf32(x.x * qscale));
        w.y = __uint_as_float(f2tf32(x.y * qscale));
        w.z = __uint_as_float(f2tf32(x.z * qscale));
        w.w = __uint_as_float(f2tf32(x.w * qscale));
        *reinterpret_cast<float4*>(QS + m * QS_STRIDE + c * 4) = w;
    }

    // Producers prefill buffer 0 with tile 0 (overlaps consumers' Q load).
    if (is_producer) {
        fill_tile(sm + KS_OFF, sm + VS_OFF, k, v, kc, vc, bt, b, hk, 0, pt);
    }
    __syncthreads();   // Q tile + K/V tile 0 ready

    // Per-thread fragment rows (mma m16n8: rows gp and gp+8 in warp tile).
    const int r0 = warp * 16 + gp;          // (only meaningful for consumers)
    const int r1 = r0 + 8;
    const int qpos_r0 = qpos0 + (r0 >> 2);
    const int qpos_r1 = qpos0 + (r1 >> 2);

    float m0 = -1e30f, m1 = -1e30f;   // running row maxima (log2 domain)
    float l0 = 0.f,    l1 = 0.f;      // running row sums
    float o[16][4];                   // O accumulator: 16 n-tiles of 8 cols
    #pragma unroll
    for (int i = 0; i < 16; i++) { o[i][0] = o[i][1] = o[i][2] = o[i][3] = 0.f; }

    const int src0 = (lane & 28) | (tig >> 1);   // P-transpose shuffle sources
    const int src2 = src0 + 2;
    const bool oddc = (tig & 1);

    for (int kt = 0; kt < nkt; kt++) {
        const int buf = kt & 1;
        float* KS = sm + KS_OFF + buf * KS_BUF;
        float* VS = sm + VS_OFF + buf * VS_BUF;

        if (is_producer) {
            // Fill the other buffer with the next tile while consumers work.
            if (kt + 1 < nkt) {
                fill_tile(sm + KS_OFF + (buf ^ 1) * KS_BUF,
                          sm + VS_OFF + (buf ^ 1) * VS_BUF,
                          k, v, kc, vc, bt, b, hk, kt + 1, pt);
            }
        } else {
            // ---- S = (Q*scale) K^T : 16 rows x 64 keys per warp ----
            float s[8][4];
            #pragma unroll
            for (int nt = 0; nt < 8; nt++) { s[nt][0]=s[nt][1]=s[nt][2]=s[nt][3]=0.f; }
            #pragma unroll
            for (int kk = 0; kk < 16; kk++) {            // D/8 k-steps
                uint32_t a0 = __float_as_uint(QS[r0 * QS_STRIDE + kk * 8 + tig]);
                uint32_t a1 = __float_as_uint(QS[r1 * QS_STRIDE + kk * 8 + tig]);
                uint32_t a2 = __float_as_uint(QS[r0 * QS_STRIDE + kk * 8 + tig + 4]);
                uint32_t a3 = __float_as_uint(QS[r1 * QS_STRIDE + kk * 8 + tig + 4]);
                #pragma unroll
                for (int nt = 0; nt < 8; nt++) {         // 64 keys / 8
                    uint32_t b0 = __float_as_uint(KS[(nt*8 + gp) * KS_STRIDE + kk*8 + tig]);
                    uint32_t b1 = __float_as_uint(KS[(nt*8 + gp) * KS_STRIDE + kk*8 + tig + 4]);
                    mma_tf32(s[nt][0], s[nt][1], s[nt][2], s[nt][3],
                             a0, a1, a2, a3, b0, b1);
                }
            }

            // ---- Causal mask (only tiles overlapping the query region) ----
            if (kt * NTILE + NTILE - 1 > qpos0) {
                #pragma unroll
                for (int nt = 0; nt < 8; nt++) {
                    int t0 = kt * NTILE + nt * 8 + 2 * tig;
                    if (t0     > qpos_r0) s[nt][0] = -1e30f;
                    if (t0 + 1 > qpos_r0) s[nt][1] = -1e30f;
                    if (t0     > qpos_r1) s[nt][2] = -1e30f;
                    if (t0 + 1 > qpos_r1) s[nt][3] = -1e30f;
                }
            }

            // ---- Online softmax (exp2 domain); exp'd P overwrites s ----
            float mx0 = -1e30f, mx1 = -1e30f;
            #pragma unroll
            for (int nt = 0; nt < 8; nt++) {
                mx0 = fmaxf(mx0, fmaxf(s[nt][0], s[nt][1]));
                mx1 = fmaxf(mx1, fmaxf(s[nt][2], s[nt][3]));
            }
            mx0 = fmaxf(mx0, __shfl_xor_sync(0xffffffffu, mx0, 1));
            mx0 = fmaxf(mx0, __shfl_xor_sync(0xffffffffu, mx0, 2));
            mx1 = fmaxf(mx1, __shfl_xor_sync(0xffffffffu, mx1, 1));
            mx1 = fmaxf(mx1, __shfl_xor_sync(0xffffffffu, mx1, 2));

            float nm0 = fmaxf(m0, mx0), nm1 = fmaxf(m1, mx1);
            float al0 = exp2f(m0 - nm0), al1 = exp2f(m1 - nm1);
            m0 = nm0; m1 = nm1;

            float ts0 = 0.f, ts1 = 0.f;
            #pragma unroll
            for (int nt = 0; nt < 8; nt++) {
                s[nt][0] = exp2f(s[nt][0] - m0);
                s[nt][1] = exp2f(s[nt][1] - m0);
                s[nt][2] = exp2f(s[nt][2] - m1);
                s[nt][3] = exp2f(s[nt][3] - m1);
                ts0 += s[nt][0] + s[nt][1];
                ts1 += s[nt][2] + s[nt][3];
            }
            ts0 += __shfl_xor_sync(0xffffffffu, ts0, 1);
            ts0 += __shfl_xor_sync(0xffffffffu, ts0, 2);
            ts1 += __shfl_xor_sync(0xffffffffu, ts1, 1);
            ts1 += __shfl_xor_sync(0xffffffffu, ts1, 2);
            l0 = l0 * al0 + ts0;
            l1 = l1 * al1 + ts1;

            #pragma unroll
            for (int nt = 0; nt < 16; nt++) {
                o[nt][0] *= al0; o[nt][1] *= al0;
                o[nt][2] *= al1; o[nt][3] *= al1;
            }

            // ---- O += P V, with P transposed C->A layout via shuffles ----
            #pragma unroll
            for (int kk = 0; kk < 8; kk++) {             // 64 keys / 8
                // A-frag element (r, 8kk+c): owner lane (gp, c>>1), comp c&1.
                float x00 = __shfl_sync(0xffffffffu, s[kk][0], src0);
                float x01 = __shfl_sync(0xffffffffu, s[kk][1], src0);
                float x10 = __shfl_sync(0xffffffffu, s[kk][2], src0);
                float x11 = __shfl_sync(0xffffffffu, s[kk][3], src0);
                float y00 = __shfl_sync(0xffffffffu, s[kk][0], src2);
                float y01 = __shfl_sync(0xffffffffu, s[kk][1], src2);
                float y10 = __shfl_sync(0xffffffffu, s[kk][2], src2);
                float y11 = __shfl_sync(0xffffffffu, s[kk][3], src2);
                uint32_t a0 = f2tf32(oddc ? x01 : x00);
                uint32_t a1 = f2tf32(oddc ? x11 : x10);
                uint32_t a2 = f2tf32(oddc ? y01 : y00);
                uint32_t a3 = f2tf32(oddc ? y11 : y10);
                #pragma unroll
                for (int nt = 0; nt < 16; nt++) {        // D/8 output n-tiles
                    uint32_t b0 = __float_as_uint(VS[(kk*8 + tig)     * VS_STRIDE + nt*8 + gp]);
                    uint32_t b1 = __float_as_uint(VS[(kk*8 + tig + 4) * VS_STRIDE + nt*8 + gp]);
                    mma_tf32(o[nt][0], o[nt][1], o[nt][2], o[nt][3],
                             a0, a1, a2, a3, b0, b1);
                }
            }
        }

        __syncthreads();   // next buffer filled; current buffer consumed
    }

    // ---- Epilogue: normalize and store (compute warps only) ----
    if (!is_producer) {
        const float inv0 = 1.f / l0;
        const float inv1 = 1.f / l1;
        const long orow0 = ((long)(b * Q_ + qt * TQ + (r0 >> 2)) * H_ + hk * G_ + (r0 & 3)) * D_;
        const long orow1 = ((long)(b * Q_ + qt * TQ + (r1 >> 2)) * H_ + hk * G_ + (r1 & 3)) * D_;
        #pragma unroll
        for (int nt = 0; nt < 16; nt++) {
            int cc = nt * 8 + 2 * tig;
            float2 w0 = make_float2(o[nt][0] * inv0, o[nt][1] * inv0);
            float2 w1 = make_float2(o[nt][2] * inv1, o[nt][3] * inv1);
            *reinterpret_cast<float2*>(out + orow0 + cc) = w0;
            *reinterpret_cast<float2*>(out + orow1 + cc) = w1;
        }
    }
}

}  // namespace

extern "C" void kernel_launch(void* const* d_in, const int* in_sizes, int n_in,
                              void* d_out, int out_size) {
    const float* q  = (const float*)d_in[0];
    const float* k  = (const float*)d_in[1];
    const float* v  = (const float*)d_in[2];
    const float* kc = (const float*)d_in[3];
    const float* vc = (const float*)d_in[4];
    const int*   bt = (const int*)d_in[5];
    float* out = (float*)d_out;

    cudaFuncSetAttribute(attn_kernel,
                         cudaFuncAttributeMaxDynamicSharedMemorySize, SMEM_BYTES);

    dim3 grid(Q_ / TQ, HK_, B_);   // qt fastest -> same-(b,hk) blocks share L2
    attn_kernel<<<grid, THREADS, SMEM_BYTES>>>(q, k, v, kc, vc, bt, out);
}

// round 11
// speedup vs baseline: 1.5696x; 1.0955x over previous
#include <cuda_runtime.h>
#include <cuda_fp16.h>
#include <cstdint>

// ---------------------------------------------------------------------------
// Paged-attention prefill-extend, fp16 mma.sync.m16n8k16 flash-attention (v3b).
//   B=4, Q=512 new tokens/seq, P=2048 cached, L=2560, BS=16,
//   H=32 q-heads, HK=8 kv-heads (G=4), D=128, fp32 in/out.
//
// v3 -> v3b: fix smem strides. Q/K rows hold 128 halves, so QST/KST must be
// >= 128 (now 136: 68 words == 4 mod 32 -> conflict-free fragments). VT rows
// hold 64 halves, VTST stays 72 (36 words == 4 mod 32).
// (R10: resubmitted unchanged — R9 bench was a broker infra failure.)
//
// Cache-scatter elimination: the gather for t >= P returns exactly the fresh
// k/v rows, so read them directly; caches are never written (graph-safe).
//
// One CTA = (b, hk, 32-query tile): M=128 rows (32 pos x 4 g-heads sharing
// K/V), 64 keys per mainloop tile.
//   warps 0..7  : compute (16 M-rows each) - QK^T, online softmax, PV.
//                 S's C-fragment layout == PV's A-fragment layout, so P never
//                 touches smem or shuffles (pack half2 straight from regs).
//   warps 8..11 : producers - gather K/V (fp32), convert fp16, STS into
//                 double-buffered K (row-major) and V^T (dim-major) tiles.
// ---------------------------------------------------------------------------

#define DEVFN __device__ __forceinline__

namespace {

constexpr int B_  = 4;
constexpr int Q_  = 512;
constexpr int P_  = 2048;
constexpr int H_  = 32;
constexpr int HK_ = 8;
constexpr int D_  = 128;
constexpr int G_  = 4;
constexpr int NPAGES = 160;

constexpr int TQ      = 32;
constexpr int MTILE   = 128;
constexpr int NTILE   = 64;
constexpr int NCWARP  = 8;
constexpr int NPWARP  = 4;
constexpr int THREADS = (NCWARP + NPWARP) * 32;   // 384

// Strides in halves. Fragment loads touch word offsets (row*(ST/2) + tig);
// ST/2 mod 32 == 4 makes all 8 gp-rows x 4 tig-words hit 32 distinct banks.
constexpr int QST = 136;   // >= 128 content halves
constexpr int KST = 136;   // >= 128 content halves
constexpr int VTST = 72;   // >= 64 content halves

constexpr int QS_OFF = 0;                       // 128 x 136 halves
constexpr int KS_OFF = MTILE * QST;             // 17408
constexpr int KS_BUF = NTILE * KST;             // 8704
constexpr int VT_OFF = KS_OFF + 2 * KS_BUF;     // 34816
constexpr int VT_BUF = D_ * VTST;               // 9216 (V^T: 128 dims x 64 keys)
constexpr int SMEM_HALVES = VT_OFF + 2 * VT_BUF;   // 53248
constexpr int SMEM_BYTES  = SMEM_HALVES * 2;       // 106496 B

DEVFN uint32_t h2u(__half2 h) { return *reinterpret_cast<uint32_t*>(&h); }
DEVFN uint32_t packh2(float a, float b) { return h2u(__floats2half2_rn(a, b)); }

DEVFN void mma_f16(float& c0, float& c1, float& c2, float& c3,
                   uint32_t a0, uint32_t a1, uint32_t a2, uint32_t a3,
                   uint32_t b0, uint32_t b1) {
    asm volatile(
        "mma.sync.aligned.m16n8k16.row.col.f32.f16.f16.f32 "
        "{%0,%1,%2,%3}, {%4,%5,%6,%7}, {%8,%9}, {%0,%1,%2,%3};"
        : "+f"(c0), "+f"(c1), "+f"(c2), "+f"(c3)
        : "r"(a0), "r"(a1), "r"(a2), "r"(a3), "r"(b0), "r"(b1));
}

// Pointer to the D=128 fp32 row for key/value position t of (b, hk).
DEVFN const float4* kv_row(const float* __restrict__ cache,
                           const float* __restrict__ fresh,
                           const int* __restrict__ bt,
                           int b, int hk, int t) {
    if (t < P_) {
        int page = bt[b * NPAGES + (t >> 4)];
        long slot = (long)page * 16 + (t & 15);
        return reinterpret_cast<const float4*>(cache + (slot * HK_ + hk) * D_);
    }
    long row = (long)(b * Q_ + (t - P_)) * HK_ + hk;
    return reinterpret_cast<const float4*>(fresh + row * D_);
}

// Producer: fill K (row-major, fp16) and V^T (dim-major, fp16) for tile kt.
DEVFN void fill_tile(__half* __restrict__ KSb, __half* __restrict__ VTb,
                     const float* __restrict__ k, const float* __restrict__ v,
                     const float* __restrict__ kc, const float* __restrict__ vc,
                     const int* __restrict__ bt,
                     int b, int hk, int kt, int pt) {
    // K: 64 keys x 32 float4-chunks -> contiguous 4-half stores.
    #pragma unroll
    for (int i = pt; i < NTILE * 32; i += NPWARP * 32) {
        int j = i >> 5, c = i & 31;
        float4 x = kv_row(kc, k, bt, b, hk, kt * NTILE + j)[c];
        uint2 w;
        w.x = packh2(x.x, x.y);
        w.y = packh2(x.z, x.w);
        *reinterpret_cast<uint2*>(KSb + j * KST + 4 * c) = w;
    }
    // V^T: key-pairs x 32 dim-chunks; half2 = (key 2u, key 2u+1) per dim.
    #pragma unroll
    for (int i = pt; i < (NTILE / 2) * 32; i += NPWARP * 32) {
        int u = i & 31, c = i >> 5;
        float4 va = kv_row(vc, v, bt, b, hk, kt * NTILE + 2 * u)[c];
        float4 vb = kv_row(vc, v, bt, b, hk, kt * NTILE + 2 * u + 1)[c];
        *reinterpret_cast<uint32_t*>(VTb + (4*c+0) * VTST + 2*u) = packh2(va.x, vb.x);
        *reinterpret_cast<uint32_t*>(VTb + (4*c+1) * VTST + 2*u) = packh2(va.y, vb.y);
        *reinterpret_cast<uint32_t*>(VTb + (4*c+2) * VTST + 2*u) = packh2(va.z, vb.z);
        *reinterpret_cast<uint32_t*>(VTb + (4*c+3) * VTST + 2*u) = packh2(va.w, vb.w);
    }
}

__global__ __launch_bounds__(THREADS, 1)
void attn_kernel(const float* __restrict__ q,  const float* __restrict__ k,
                 const float* __restrict__ v,  const float* __restrict__ kc,
                 const float* __restrict__ vc, const int*   __restrict__ bt,
                 float* __restrict__ out) {
    extern __shared__ __half sm[];
    __half* QS = sm + QS_OFF;

    const int tid  = threadIdx.x;
    const int warp = tid >> 5;
    const int lane = tid & 31;
    const int gp   = lane >> 2;
    const int tig  = lane & 3;

    const int qt = blockIdx.x;
    const int hk = blockIdx.y;
    const int b  = blockIdx.z;

    const int qpos0 = P_ + qt * TQ;
    const int nkt   = (qpos0 + TQ + NTILE - 1) / NTILE;

    const bool is_producer = (warp >= NCWARP);
    const int  pt = tid - NCWARP * 32;

    // Fold D^-1/2 and log2(e) into Q: scores live in the exp2 domain.
    const float qscale = 0.088388347648318447f * 1.4426950408889634f;

    // ---- Cooperative Q load + scale + fp16 convert (all 384 threads) ----
    for (int i = tid; i < MTILE * 32; i += THREADS) {
        int m = i >> 5, c = i & 31;
        const float4* qp = reinterpret_cast<const float4*>(
            q + ((long)(b * Q_ + qt * TQ + (m >> 2)) * H_ + hk * G_ + (m & 3)) * D_);
        float4 x = qp[c];
        uint2 w;
        w.x = packh2(x.x * qscale, x.y * qscale);
        w.y = packh2(x.z * qscale, x.w * qscale);
        *reinterpret_cast<uint2*>(QS + m * QST + 4 * c) = w;
    }
    if (is_producer) {
        fill_tile(sm + KS_OFF, sm + VT_OFF, k, v, kc, vc, bt, b, hk, 0, pt);
    }
    __syncthreads();   // Q + K/V tile 0 ready

    const int r0 = warp * 16 + gp;
    const int r1 = r0 + 8;
    const int qpos_r0 = qpos0 + (r0 >> 2);
    const int qpos_r1 = qpos0 + (r1 >> 2);

    float m0 = -1e30f, m1 = -1e30f;
    float l0 = 0.f,    l1 = 0.f;
    float o[16][4];
    #pragma unroll
    for (int i = 0; i < 16; i++) { o[i][0] = o[i][1] = o[i][2] = o[i][3] = 0.f; }

    for (int kt = 0; kt < nkt; kt++) {
        const int buf = kt & 1;
        __half* KS = sm + KS_OFF + buf * KS_BUF;
        __half* VT = sm + VT_OFF + buf * VT_BUF;

        if (is_producer) {
            if (kt + 1 < nkt) {
                fill_tile(sm + KS_OFF + (buf ^ 1) * KS_BUF,
                          sm + VT_OFF + (buf ^ 1) * VT_BUF,
                          k, v, kc, vc, bt, b, hk, kt + 1, pt);
            }
        } else {
            // ---- S = Q K^T : 16 rows x 64 keys, 8 k16-steps over D=128 ----
            float s[8][4];
            #pragma unroll
            for (int nt = 0; nt < 8; nt++) { s[nt][0]=s[nt][1]=s[nt][2]=s[nt][3]=0.f; }
            #pragma unroll
            for (int ks = 0; ks < 8; ks++) {
                const __half* qa = QS + ks * 16 + 2 * tig;
                uint32_t a0 = *reinterpret_cast<const uint32_t*>(qa + r0 * QST);
                uint32_t a1 = *reinterpret_cast<const uint32_t*>(qa + r1 * QST);
                uint32_t a2 = *reinterpret_cast<const uint32_t*>(qa + r0 * QST + 8);
                uint32_t a3 = *reinterpret_cast<const uint32_t*>(qa + r1 * QST + 8);
                #pragma unroll
                for (int nt = 0; nt < 8; nt++) {
                    const __half* kb = KS + (nt * 8 + gp) * KST + ks * 16 + 2 * tig;
                    uint32_t b0 = *reinterpret_cast<const uint32_t*>(kb);
                    uint32_t b1 = *reinterpret_cast<const uint32_t*>(kb + 8);
                    mma_f16(s[nt][0], s[nt][1], s[nt][2], s[nt][3],
                            a0, a1, a2, a3, b0, b1);
                }
            }

            // ---- Causal mask ----
            if (kt * NTILE + NTILE - 1 > qpos0) {
                #pragma unroll
                for (int nt = 0; nt < 8; nt++) {
                    int t0 = kt * NTILE + nt * 8 + 2 * tig;
                    if (t0     > qpos_r0) s[nt][0] = -1e30f;
                    if (t0 + 1 > qpos_r0) s[nt][1] = -1e30f;
                    if (t0     > qpos_r1) s[nt][2] = -1e30f;
                    if (t0 + 1 > qpos_r1) s[nt][3] = -1e30f;
                }
            }

            // ---- Online softmax (exp2 domain); exp'd P overwrites s ----
            float mx0 = -1e30f, mx1 = -1e30f;
            #pragma unroll
            for (int nt = 0; nt < 8; nt++) {
                mx0 = fmaxf(mx0, fmaxf(s[nt][0], s[nt][1]));
                mx1 = fmaxf(mx1, fmaxf(s[nt][2], s[nt][3]));
            }
            mx0 = fmaxf(mx0, __shfl_xor_sync(0xffffffffu, mx0, 1));
            mx0 = fmaxf(mx0, __shfl_xor_sync(0xffffffffu, mx0, 2));
            mx1 = fmaxf(mx1, __shfl_xor_sync(0xffffffffu, mx1, 1));
            mx1 = fmaxf(mx1, __shfl_xor_sync(0xffffffffu, mx1, 2));

            float nm0 = fmaxf(m0, mx0), nm1 = fmaxf(m1, mx1);
            float al0 = exp2f(m0 - nm0), al1 = exp2f(m1 - nm1);
            m0 = nm0; m1 = nm1;

            float ts0 = 0.f, ts1 = 0.f;
            #pragma unroll
            for (int nt = 0; nt < 8; nt++) {
                s[nt][0] = exp2f(s[nt][0] - m0);
                s[nt][1] = exp2f(s[nt][1] - m0);
                s[nt][2] = exp2f(s[nt][2] - m1);
                s[nt][3] = exp2f(s[nt][3] - m1);
                ts0 += s[nt][0] + s[nt][1];
                ts1 += s[nt][2] + s[nt][3];
            }
            ts0 += __shfl_xor_sync(0xffffffffu, ts0, 1);
            ts0 += __shfl_xor_sync(0xffffffffu, ts0, 2);
            ts1 += __shfl_xor_sync(0xffffffffu, ts1, 1);
            ts1 += __shfl_xor_sync(0xffffffffu, ts1, 2);
            l0 = l0 * al0 + ts0;
            l1 = l1 * al1 + ts1;

            #pragma unroll
            for (int nt = 0; nt < 16; nt++) {
                o[nt][0] *= al0; o[nt][1] *= al0;
                o[nt][2] *= al1; o[nt][3] *= al1;
            }

            // ---- O += P V : S's C-layout IS the fp16 A-layout (pack only) --
            #pragma unroll
            for (int kk = 0; kk < 4; kk++) {           // 64 keys / 16
                uint32_t a0 = packh2(s[2*kk  ][0], s[2*kk  ][1]);   // r0, k[0:8)
                uint32_t a1 = packh2(s[2*kk  ][2], s[2*kk  ][3]);   // r1, k[0:8)
                uint32_t a2 = packh2(s[2*kk+1][0], s[2*kk+1][1]);   // r0, k[8:16)
                uint32_t a3 = packh2(s[2*kk+1][2], s[2*kk+1][3]);   // r1, k[8:16)
                #pragma unroll
                for (int nt = 0; nt < 16; nt++) {      // D/8 output n-tiles
                    const __half* vb = VT + (nt * 8 + gp) * VTST + kk * 16 + 2 * tig;
                    uint32_t b0 = *reinterpret_cast<const uint32_t*>(vb);
                    uint32_t b1 = *reinterpret_cast<const uint32_t*>(vb + 8);
                    mma_f16(o[nt][0], o[nt][1], o[nt][2], o[nt][3],
                            a0, a1, a2, a3, b0, b1);
                }
            }
        }

        __syncthreads();   // next buffer filled; current buffer consumed
    }

    // ---- Epilogue: normalize and store (compute warps only) ----
    if (!is_producer) {
        const float inv0 = 1.f / l0;
        const float inv1 = 1.f / l1;
        const long orow0 = ((long)(b * Q_ + qt * TQ + (r0 >> 2)) * H_ + hk * G_ + (r0 & 3)) * D_;
        const long orow1 = ((long)(b * Q_ + qt * TQ + (r1 >> 2)) * H_ + hk * G_ + (r1 & 3)) * D_;
        #pragma unroll
        for (int nt = 0; nt < 16; nt++) {
            int cc = nt * 8 + 2 * tig;
            float2 w0 = make_float2(o[nt][0] * inv0, o[nt][1] * inv0);
            float2 w1 = make_float2(o[nt][2] * inv1, o[nt][3] * inv1);
            *reinterpret_cast<float2*>(out + orow0 + cc) = w0;
            *reinterpret_cast<float2*>(out + orow1 + cc) = w1;
        }
    }
}

}  // namespace

extern "C" void kernel_launch(void* const* d_in, const int* in_sizes, int n_in,
                              void* d_out, int out_size) {
    const float* q  = (const float*)d_in[0];
    const float* k  = (const float*)d_in[1];
    const float* v  = (const float*)d_in[2];
    const float* kc = (const float*)d_in[3];
    const float* vc = (const float*)d_in[4];
    const int*   bt = (const int*)d_in[5];
    float* out = (float*)d_out;

    cudaFuncSetAttribute(attn_kernel,
                         cudaFuncAttributeMaxDynamicSharedMemorySize, SMEM_BYTES);

    dim3 grid(Q_ / TQ, HK_, B_);   // qt fastest -> same-(b,hk) blocks share L2
    attn_kernel<<<grid, THREADS, SMEM_BYTES>>>(q, k, v, kc, vc, bt, out);
}